// round 13
// baseline (speedup 1.0000x reference)
#include <cuda_runtime.h>
#include <cstdint>

#define BB      16
#define HH      32
#define DD      128
#define HIDDEN  4096      // HH*DD
#define MB      128
#define BSZ     16
#define SMAX    2048      // MB*BSZ
#define SPLITS  64
#define SPLIT_P 32                // positions per CTA (2 cache blocks)
#define NW      8
#define NT      (NW * 32)         // 256 threads
#define POSF    (HH * DD)         // 4096 floats per position (16 KB)
#define NSTAGE  3
#define SMEM_DYN_BYTES (NSTAGE * POSF * 2 * 4)   // 96 KB (K + V rings)
#define EPS     1e-6f
#define SCALE   0.08838834764831845f   // 1/sqrt(128)

// Persistent device scratch
__device__ float g_q [BB * HIDDEN];
__device__ float g_pm[BB * SPLITS * HH];
__device__ float g_pl[BB * SPLITS * HH];
__device__ float g_po[BB * SPLITS * HH * DD];   // 16 MB

__device__ __forceinline__ void cp16(unsigned int dst, const void* src) {
    asm volatile("cp.async.cg.shared.global [%0], [%1], 16;"
                 :: "r"(dst), "l"(src) : "memory");
}

// ---------------------------------------------------------------------------
// Kernel 1: RMSNorm -> q.   grid = B*H = 512, block = 256.
// ---------------------------------------------------------------------------
__global__ void __launch_bounds__(256) rms_kernel(const float* __restrict__ x,
                                                  const float* __restrict__ w) {
    int bh  = blockIdx.x;
    int h   = bh & (HH - 1);
    int b   = bh >> 5;
    int tid = threadIdx.x;
    int warp = tid >> 5, lane = tid & 31;

    const float4* xp = (const float4*)(x + (size_t)b * HIDDEN);

    float s = 0.f;
#pragma unroll
    for (int i = 0; i < 4; i++) {
        float4 v = xp[tid + i * 256];
        s += v.x * v.x + v.y * v.y + v.z * v.z + v.w * v.w;
    }
    __shared__ float red[8];
#pragma unroll
    for (int o = 16; o; o >>= 1) s += __shfl_xor_sync(0xffffffffu, s, o);
    if (lane == 0) red[warp] = s;
    __syncthreads();
    float t = red[0];
#pragma unroll
    for (int i = 1; i < 8; i++) t += red[i];
    float inv = rsqrtf(t * (1.0f / HIDDEN) + EPS);

    if (tid < 32) {
        float4 hv = xp[h * 32 + tid];
        float4 wv = ((const float4*)w)[h * 32 + tid];
        float4 q;
        q.x = hv.x * inv * wv.x;
        q.y = hv.y * inv * wv.y;
        q.z = hv.z * inv * wv.z;
        q.w = hv.w * inv * wv.w;
        ((float4*)(g_q + (size_t)b * HIDDEN + h * DD))[tid] = q;
    }
}

// ---------------------------------------------------------------------------
// Kernel 2: all-heads contiguous-stream flash-decoding partial.
// grid = B*SPLITS = 1024, block = 256 (8 warps, warp owns 4 heads).
// Per stage: one position = 16 KB K + 16 KB V, fully contiguous cp.async.
// ---------------------------------------------------------------------------
__global__ void __launch_bounds__(NT) attn_partial(
        const float* __restrict__ kc,
        const float* __restrict__ vc,
        const int*   __restrict__ bt,
        const int*   __restrict__ ctx) {

    extern __shared__ float smdyn[];
    float* kbuf = smdyn;                    // [NSTAGE][POSF]
    float* vbuf = smdyn + NSTAGE * POSF;    // [NSTAGE][POSF]
    __shared__ int sblk[SPLIT_P / BSZ];     // 2 cache-block ids

    int idx   = blockIdx.x;
    int split = idx & (SPLITS - 1);
    int b     = idx >> 6;
    int tid   = threadIdx.x;
    int warp  = tid >> 5;
    int lane  = tid & 31;
    int h0    = warp * 4;

    int n_ctx = ctx[b];
    int start = split * SPLIT_P;
    int n     = min(n_ctx - start, SPLIT_P);
    if (n <= 0) return;    // combine loops only over live splits

    if (tid < SPLIT_P / BSZ)
        sblk[tid] = bt[b * MB + (start >> 4) + tid];

    // q for this warp's 4 heads: one float4 per lane per head
    float4 qv[4];
#pragma unroll
    for (int j = 0; j < 4; j++)
        qv[j] = ((const float4*)(g_q + (size_t)b * HIDDEN + (h0 + j) * DD))[lane];
    __syncthreads();   // sblk visible

    unsigned int kaddr = (unsigned int)__cvta_generic_to_shared(kbuf);
    unsigned int vaddr = (unsigned int)__cvta_generic_to_shared(vbuf);

    auto copy_stage = [&](int s) {
        if (s < n) {
            int sp = start + s;
            size_t base = ((size_t)sblk[s >> 4] * BSZ + (sp & 15)) * POSF;
            const char* ks = (const char*)(kc + base);
            const char* vs = (const char*)(vc + base);
            unsigned int kd = kaddr + (unsigned int)((s % NSTAGE) * POSF * 4);
            unsigned int vd = vaddr + (unsigned int)((s % NSTAGE) * POSF * 4);
#pragma unroll
            for (int i = 0; i < 4; i++) {
                int off = (tid + 256 * i) << 4;
                cp16(kd + off, ks + off);
                cp16(vd + off, vs + off);
            }
        }
        asm volatile("cp.async.commit_group;" ::: "memory");
    };

    copy_stage(0);
    copy_stage(1);

    float4 acc[4];
    float  mh[4], lh[4];
#pragma unroll
    for (int j = 0; j < 4; j++) {
        acc[j] = make_float4(0.f, 0.f, 0.f, 0.f);
        mh[j]  = -1e30f;
        lh[j]  = 0.f;
    }

    for (int s = 0; s < n; s++) {
        asm volatile("cp.async.wait_group 1;" ::: "memory");
        __syncthreads();           // stage s ready; compute(s-1) done by all
        copy_stage(s + 2);         // overwrites buffer (s-1)%NSTAGE

        const float* kb = kbuf + (s % NSTAGE) * POSF;
        const float* vb = vbuf + (s % NSTAGE) * POSF;

        float p[4];
#pragma unroll
        for (int j = 0; j < 4; j++) {
            float4 kv = ((const float4*)(kb + (h0 + j) * DD))[lane];
            p[j] = qv[j].x * kv.x + qv[j].y * kv.y +
                   qv[j].z * kv.z + qv[j].w * kv.w;
        }
#pragma unroll
        for (int j = 0; j < 4; j++) {
#pragma unroll
            for (int o = 16; o; o >>= 1)
                p[j] += __shfl_xor_sync(0xffffffffu, p[j], o);
            p[j] *= SCALE;         // warp-uniform now
        }

#pragma unroll
        for (int j = 0; j < 4; j++) {
            float4 vv = ((const float4*)(vb + (h0 + j) * DD))[lane];
            if (p[j] > mh[j]) {    // warp-uniform branch
                float r = __expf(mh[j] - p[j]);   // -> 0 on first hit
                mh[j] = p[j];
                lh[j] = lh[j] * r + 1.f;          // e = exp(0) = 1
                acc[j].x = acc[j].x * r + vv.x;
                acc[j].y = acc[j].y * r + vv.y;
                acc[j].z = acc[j].z * r + vv.z;
                acc[j].w = acc[j].w * r + vv.w;
            } else {
                float e = __expf(p[j] - mh[j]);
                lh[j] += e;
                acc[j].x += e * vv.x;
                acc[j].y += e * vv.y;
                acc[j].z += e * vv.z;
                acc[j].w += e * vv.w;
            }
        }
    }

    // ---- epilogue: publish per-head partials ----
#pragma unroll
    for (int j = 0; j < 4; j++) {
        int ph = idx * HH + h0 + j;
        if (lane == 0) { g_pm[ph] = mh[j]; g_pl[ph] = lh[j]; }
        ((float4*)(g_po + (size_t)ph * DD))[lane] = acc[j];
    }
}

// ---------------------------------------------------------------------------
// Kernel 3: combine live splits + residual.  grid = B*H = 512, block = 128.
// ---------------------------------------------------------------------------
__global__ void __launch_bounds__(DD) combine_kernel(
        const float* __restrict__ hidden,
        const int*   __restrict__ ctx,
        float*       __restrict__ out) {
    int bh = blockIdx.x;
    int h  = bh & (HH - 1);
    int b  = bh >> 5;
    int d  = threadIdx.x;

    int ns = (ctx[b] + SPLIT_P - 1) / SPLIT_P;   // live splits, >= 1

    float M = -1e30f;
    for (int i = 0; i < ns; i++)
        M = fmaxf(M, g_pm[(b * SPLITS + i) * HH + h]);

    float L = 0.f, A = 0.f;
    for (int i = 0; i < ns; i++) {
        int ph = (b * SPLITS + i) * HH + h;
        float wgt = __expf(g_pm[ph] - M);
        L += g_pl[ph] * wgt;
        A += wgt * g_po[(size_t)ph * DD + d];
    }

    int o = bh * DD + d;   // == b*HIDDEN + h*DD + d
    out[o] = hidden[o] + A / L;
}

// ---------------------------------------------------------------------------
extern "C" void kernel_launch(void* const* d_in, const int* in_sizes, int n_in,
                              void* d_out, int out_size) {
    const float* hidden = (const float*)d_in[0];
    const float* kc     = (const float*)d_in[1];
    const float* vc     = (const float*)d_in[2];
    const int*   bt     = (const int*)  d_in[3];
    const int*   ctx    = (const int*)  d_in[4];
    const float* w      = (const float*)d_in[5];
    float*       out    = (float*)d_out;

    cudaFuncSetAttribute(attn_partial,
                         cudaFuncAttributeMaxDynamicSharedMemorySize,
                         SMEM_DYN_BYTES);

    rms_kernel    <<<BB * HH,      256>>>(hidden, w);
    attn_partial  <<<BB * SPLITS,  NT, SMEM_DYN_BYTES>>>(kc, vc, bt, ctx);
    combine_kernel<<<BB * HH,      DD >>>(hidden, ctx, out);
}

// round 14
// speedup vs baseline: 1.1405x; 1.1405x over previous
#include <cuda_runtime.h>
#include <cstdint>

#define BB      16
#define HH      32
#define DD      128
#define HIDDEN  4096      // HH*DD
#define MB      128
#define BSZ     16
#define NB      1024      // num cache blocks
#define POSF    (HH * DD) // floats per cached position (16 KB)
#define EPS     1e-6f
#define SCALE   0.08838834764831845f   // 1/sqrt(128)

// Persistent device scratch
__device__ float g_q [BB * HIDDEN];
__device__ int   g_work[BB * MB];              // live (b,slot) entries, block-sorted
__device__ int   g_nwork;
__device__ float g_pm[BB * HH * MB];
__device__ float g_pl[BB * HH * MB];
__device__ float g_po[(size_t)BB * HH * MB * DD];   // 33.5 MB

// ---------------------------------------------------------------------------
// Kernel 1: RMSNorm -> q (CTAs 0..511)  +  block-sorted work list (CTA 512).
// block = 256.
// ---------------------------------------------------------------------------
__global__ void __launch_bounds__(256) rms_sched_kernel(
        const float* __restrict__ x,
        const float* __restrict__ w,
        const int*   __restrict__ bt,
        const int*   __restrict__ ctx) {

    int tid  = threadIdx.x;
    int warp = tid >> 5, lane = tid & 31;

    if (blockIdx.x < BB * HH) {
        // ---------------- RMSNorm ----------------
        int bh = blockIdx.x;
        int h  = bh & (HH - 1);
        int b  = bh >> 5;

        const float4* xp = (const float4*)(x + (size_t)b * HIDDEN);

        float s = 0.f;
#pragma unroll
        for (int i = 0; i < 4; i++) {
            float4 v = xp[tid + i * 256];
            s += v.x * v.x + v.y * v.y + v.z * v.z + v.w * v.w;
        }
        __shared__ float red[8];
#pragma unroll
        for (int o = 16; o; o >>= 1) s += __shfl_xor_sync(0xffffffffu, s, o);
        if (lane == 0) red[warp] = s;
        __syncthreads();
        float t = red[0];
#pragma unroll
        for (int i = 1; i < 8; i++) t += red[i];
        float inv = rsqrtf(t * (1.0f / HIDDEN) + EPS);

        if (tid < 32) {
            float4 hv = xp[h * 32 + tid];
            float4 wv = ((const float4*)w)[h * 32 + tid];
            float4 q;
            q.x = hv.x * inv * wv.x;
            q.y = hv.y * inv * wv.y;
            q.z = hv.z * inv * wv.z;
            q.w = hv.w * inv * wv.w;
            ((float4*)(g_q + (size_t)b * HIDDEN + h * DD))[tid] = q;
        }
    } else {
        // ---------------- counting sort of live entries by cache block ----
        __shared__ int bins [NB];
        __shared__ int obase[NB];
        __shared__ int wsum[8];
        __shared__ int stot;

        for (int i = tid; i < NB; i += 256) bins[i] = 0;
        __syncthreads();

        for (int e = tid; e < BB * MB; e += 256) {
            int b = e >> 7, slot = e & 127;
            if (slot * BSZ < ctx[b])
                atomicAdd(&bins[bt[e]], 1);
        }
        __syncthreads();

        // exclusive scan over 1024 bins (4 per thread)
        int v0 = bins[tid * 4 + 0];
        int v1 = bins[tid * 4 + 1];
        int v2 = bins[tid * 4 + 2];
        int v3 = bins[tid * 4 + 3];
        int vs = v0 + v1 + v2 + v3;

        int xacc = vs;
#pragma unroll
        for (int o = 1; o < 32; o <<= 1) {
            int y = __shfl_up_sync(0xffffffffu, xacc, o);
            if (lane >= o) xacc += y;
        }
        if (lane == 31) wsum[warp] = xacc;
        __syncthreads();
        if (tid == 0) {
            int run = 0;
#pragma unroll
            for (int i = 0; i < 8; i++) { int tt = wsum[i]; wsum[i] = run; run += tt; }
            stot = run;
        }
        __syncthreads();
        int excl = xacc - vs + wsum[warp];
        obase[tid * 4 + 0] = excl;
        obase[tid * 4 + 1] = excl + v0;
        obase[tid * 4 + 2] = excl + v0 + v1;
        obase[tid * 4 + 3] = excl + v0 + v1 + v2;
        __syncthreads();

        for (int e = tid; e < BB * MB; e += 256) {
            int b = e >> 7, slot = e & 127;
            if (slot * BSZ < ctx[b]) {
                int pos = atomicAdd(&obase[bt[e]], 1);
                g_work[pos] = e;
            }
        }
        if (tid == 0) g_nwork = stot;
    }
}

// ---------------------------------------------------------------------------
// Kernel 2: per-(entry, head-group) flash-decoding partial.
// grid = BB*MB*8 = 16384 (dead tail exits), block = 128 (4 warps).
// Warp = one head, <=16 positions of one cache block half. R6 register core.
// ---------------------------------------------------------------------------
__global__ void __launch_bounds__(128) attn_partial(
        const float* __restrict__ kc,
        const float* __restrict__ vc,
        const int*   __restrict__ bt,
        const int*   __restrict__ ctx) {

    int c   = blockIdx.x;
    int ei  = c >> 3;
    if (ei >= g_nwork) return;
    int hg  = c & 7;

    int e    = g_work[ei];
    int b    = e >> 7;
    int slot = e & 127;
    int blk  = __ldg(&bt[e]);
    int n    = min(ctx[b] - slot * BSZ, BSZ);   // 1..16 (live entries only)

    int warp = threadIdx.x >> 5;
    int lane = threadIdx.x & 31;
    int h    = hg * 4 + warp;

    float4 qv = ((const float4*)(g_q + (size_t)b * HIDDEN + h * DD))[lane];

    const float* kb = kc + (size_t)blk * BSZ * POSF + h * DD;
    const float* vb = vc + (size_t)blk * BSZ * POSF + h * DD;

    float4 acc = make_float4(0.f, 0.f, 0.f, 0.f);
    float  mw  = -1e30f;
    float  lw  = 0.f;

    for (int i0 = 0; i0 < n; i0 += 8) {
        int cnt = min(8, n - i0);

        float4 vv[8];
#pragma unroll
        for (int j = 0; j < 8; j++) {
            if (j < cnt)
                vv[j] = ((const float4*)(vb + (size_t)(i0 + j) * POSF))[lane];
        }

        float p[8];
#pragma unroll
        for (int j = 0; j < 8; j++) {
            p[j] = 0.f;
            if (j < cnt) {
                float4 kv = ((const float4*)(kb + (size_t)(i0 + j) * POSF))[lane];
                p[j] = qv.x * kv.x + qv.y * kv.y + qv.z * kv.z + qv.w * kv.w;
            }
        }
#pragma unroll
        for (int j = 0; j < 8; j++) {
#pragma unroll
            for (int o = 16; o; o >>= 1)
                p[j] += __shfl_xor_sync(0xffffffffu, p[j], o);
        }
#pragma unroll
        for (int j = 0; j < 8; j++)
            p[j] = (j < cnt) ? p[j] * SCALE : -1e30f;

        float pm = p[0];
#pragma unroll
        for (int j = 1; j < 8; j++) pm = fmaxf(pm, p[j]);
        float newm = fmaxf(mw, pm);
        float r    = __expf(mw - newm);

        float ee[8];
        float esum = 0.f;
#pragma unroll
        for (int j = 0; j < 8; j++) {
            ee[j] = __expf(p[j] - newm);
            esum += ee[j];
        }
        lw = lw * r + esum;

        acc.x *= r; acc.y *= r; acc.z *= r; acc.w *= r;
#pragma unroll
        for (int j = 0; j < 8; j++) {
            if (j < cnt) {
                acc.x += ee[j] * vv[j].x;
                acc.y += ee[j] * vv[j].y;
                acc.z += ee[j] * vv[j].z;
                acc.w += ee[j] * vv[j].w;
            }
        }
        mw = newm;
    }

    // ---- publish per-(b,h,slot) partial ----
    size_t ph = ((size_t)b * HH + h) * MB + slot;
    if (lane == 0) { g_pm[ph] = mw; g_pl[ph] = lw; }
    ((float4*)(g_po + ph * DD))[lane] = acc;
}

// ---------------------------------------------------------------------------
// Kernel 3: combine live slot-partials + residual.  grid = B*H, block = 128.
// ---------------------------------------------------------------------------
__global__ void __launch_bounds__(DD) combine_kernel(
        const float* __restrict__ hidden,
        const int*   __restrict__ ctx,
        float*       __restrict__ out) {
    int bh = blockIdx.x;          // == b*HH + h
    int b  = bh >> 5;
    int d  = threadIdx.x;

    int ns = (ctx[b] + BSZ - 1) / BSZ;   // live slots, >= 1

    float M = -1e30f;
    for (int i = 0; i < ns; i++)
        M = fmaxf(M, g_pm[(size_t)bh * MB + i]);

    float L = 0.f, A = 0.f;
    for (int i = 0; i < ns; i++) {
        size_t ph = (size_t)bh * MB + i;
        float wgt = __expf(g_pm[ph] - M);
        L += g_pl[ph] * wgt;
        A += wgt * g_po[ph * DD + d];
    }

    int o = bh * DD + d;   // == b*HIDDEN + h*DD + d
    out[o] = hidden[o] + A / L;
}

// ---------------------------------------------------------------------------
extern "C" void kernel_launch(void* const* d_in, const int* in_sizes, int n_in,
                              void* d_out, int out_size) {
    const float* hidden = (const float*)d_in[0];
    const float* kc     = (const float*)d_in[1];
    const float* vc     = (const float*)d_in[2];
    const int*   bt     = (const int*)  d_in[3];
    const int*   ctx    = (const int*)  d_in[4];
    const float* w      = (const float*)d_in[5];
    float*       out    = (float*)d_out;

    rms_sched_kernel<<<BB * HH + 1,  256>>>(hidden, w, bt, ctx);
    attn_partial    <<<BB * MB * 8,  128>>>(kc, vc, bt, ctx);
    combine_kernel  <<<BB * HH,      DD >>>(hidden, ctx, out);
}